// round 9
// baseline (speedup 1.0000x reference)
#include <cuda_runtime.h>

#define BB 2
#define NN 16384
#define SS 4096
#define KSAMP 32
#define CF 64
#define D1 64
#define D2 64
#define D3 128

typedef unsigned long long u64;

// scratch (__device__ globals per allocation rule)
__device__ __align__(16) float4 g_pts[BB * NN];   // x,y,z,|p|^2
__device__ __align__(16) float  g_px[BB * NN];
__device__ __align__(16) float  g_py[BB * NN];
__device__ __align__(16) float  g_pz[BB * NN];
__device__ __align__(16) float  g_F1[BB * NN * D1];
__device__ __align__(16) int    g_idx[BB * SS * KSAMP];

#define OUT_FEAT_BASE (BB * SS * 3)
#define OUT_SAMP_BASE (BB * SS * 3 + BB * D3 * SS)

// ---- packed f32x2 helpers -------------------------------------------------
__device__ __forceinline__ u64 fma2(u64 a, u64 b, u64 c) {
    u64 d;
    asm("fma.rn.f32x2 %0, %1, %2, %3;" : "=l"(d) : "l"(a), "l"(b), "l"(c));
    return d;
}
__device__ __forceinline__ u64 pack2(float lo, float hi) {
    u64 d;
    asm("mov.b64 %0, {%1, %2};" : "=l"(d) : "f"(lo), "f"(hi));
    return d;
}
__device__ __forceinline__ void unpack2(u64 v, float& lo, float& hi) {
    asm("mov.b64 {%0, %1}, %2;" : "=f"(lo), "=f"(hi) : "l"(v));
}

// ---------------------------------------------------------------------------
__global__ void prep_pts(const float* __restrict__ xyz, float* __restrict__ out) {
    int i = blockIdx.x * blockDim.x + threadIdx.x;
    if (i >= BB * NN) return;
    int b = i / NN, n = i % NN;
    float x = xyz[i * 3 + 0], y = xyz[i * 3 + 1], z = xyz[i * 3 + 2];
    float nn = x * x + y * y + z * z;
    g_pts[i] = make_float4(x, y, z, nn);
    g_px[i] = x; g_py[i] = y; g_pz[i] = z;
    if (n < SS) {
        int o = (b * SS + n) * 3;
        out[o + 0] = x; out[o + 1] = y; out[o + 2] = z;
        out[OUT_SAMP_BASE + b * SS + n] = (float)n;
    }
}

// ---------------------------------------------------------------------------
// F1[b][n][co] = b1[co] + sum_c feats[b][c][n] * W1[3+c][co]
__global__ void prep_F1(const float* __restrict__ feats, const float* __restrict__ W1,
                        const float* __restrict__ b1) {
    __shared__ float Ws[CF * D1];
    __shared__ float ft[CF][64 + 1];
    int t = threadIdx.x;
    int tile = blockIdx.x;
    int b = tile / (NN / 64);
    int n0 = (tile % (NN / 64)) * 64;

    for (int e = t; e < CF * D1; e += 256) Ws[e] = W1[(3 + e / D1) * D1 + (e % D1)];
    for (int e = t; e < CF * 64; e += 256) {
        int c = e >> 6, nl = e & 63;
        ft[c][nl] = feats[(b * CF + c) * NN + n0 + nl];
    }
    __syncthreads();

    int nl = t & 63;
    int cog = t >> 6;
    float acc[16];
#pragma unroll
    for (int j = 0; j < 16; j++) acc[j] = b1[cog * 16 + j];
    for (int c = 0; c < CF; c++) {
        float f = ft[c][nl];
        const float4* w4 = (const float4*)&Ws[c * D1 + cog * 16];
#pragma unroll
        for (int q = 0; q < 4; q++) {
            float4 w = w4[q];
            acc[q * 4 + 0] = fmaf(f, w.x, acc[q * 4 + 0]);
            acc[q * 4 + 1] = fmaf(f, w.y, acc[q * 4 + 1]);
            acc[q * 4 + 2] = fmaf(f, w.z, acc[q * 4 + 2]);
            acc[q * 4 + 3] = fmaf(f, w.w, acc[q * 4 + 3]);
        }
    }
    float4* dst = (float4*)&g_F1[(size_t)(b * NN + n0 + nl) * D1 + cog * 16];
#pragma unroll
    for (int q = 0; q < 4; q++)
        dst[q] = make_float4(acc[q * 4 + 0], acc[q * 4 + 1], acc[q * 4 + 2], acc[q * 4 + 3]);
}

// ---------------------------------------------------------------------------
__global__ void __launch_bounds__(256) ballq() {
    const float R2 = (float)(0.4 * 0.4);
    __shared__ float tx[256], ty[256], tz[256];
    int t = threadIdx.x;
    int lane = t & 31;
    int w = t >> 5;
    int cid = blockIdx.x * 8 + w;
    int b = cid / SS, s = cid % SS;
    const float* px = g_px + b * NN;
    const float* py = g_py + b * NN;
    const float* pz = g_pz + b * NN;

    float cx = px[s], cy = py[s], cz = pz[s];
    float cw = cx * cx + cy * cy + cz * cz;

    int cnt = 0, first = 0;
    for (int base = 0; base < NN; base += 256) {
        __syncthreads();
        tx[t] = px[base + t]; ty[t] = py[base + t]; tz[t] = pz[base + t];
        __syncthreads();
        if (cnt < KSAMP) {
#pragma unroll
            for (int j = 0; j < 8; j++) {
                int li = j * 32 + lane;
                float qx = tx[li], qy = ty[li], qz = tz[li];
                float dot = cx * qx + cy * qy + cz * qz;
                float qw = qx * qx + qy * qy + qz * qz;
                float d2 = (cw + qw) - 2.0f * dot;
                bool hit = d2 < R2;
                unsigned m = __ballot_sync(0xffffffffu, hit);
                if (m) {
                    if (cnt == 0) first = base + j * 32 + (__ffs(m) - 1);
                    int pos = cnt + __popc(m & ((1u << lane) - 1u));
                    if (hit && pos < KSAMP) g_idx[cid * KSAMP + pos] = base + j * 32 + lane;
                    cnt += __popc(m);
                    if (cnt >= KSAMP) break;
                }
            }
        }
        if (__syncthreads_and(cnt >= KSAMP)) break;
    }
    if (lane >= cnt) g_idx[cid * KSAMP + lane] = first;
}

// ---------------------------------------------------------------------------
// MLP v8: same structure as v7 (8k x 8d FFMA2 register tiles, transposed
// h[c][k] stride-34, broadcast weight LDS.128) but 16 warps/SM for latency
// hiding. smem = 50.9KB weights + 16*8.5KB = 190KB; regs capped at 128.
#define MW 16
#define MTHR 512
#define MGRID 148
#define HST 34
#define WFLO (D1 * HST)
#define WOFF (D1*D2 + D2*D3 + 3*64 + D2 + D3)
#define MLP_SMEM ((WOFF + MW * WFLO) * 4)

__global__ void __launch_bounds__(MTHR, 1) mlp_kernel(
    const float* __restrict__ W1, const float* __restrict__ W2,
    const float* __restrict__ b2, const float* __restrict__ W3,
    const float* __restrict__ b3, float* __restrict__ out) {
    extern __shared__ float sm[];
    float* W2s = sm;                         // 64*64, [c][d]
    float* W3s = W2s + D1 * D2;              // 64*128, [c][d]
    float* w1s = W3s + D2 * D3;              // 3*64
    float* b2s = w1s + 3 * 64;               // 64
    float* b3s = b2s + D2;                   // 128
    int t = threadIdx.x, lane = t & 31, w = t >> 5;
    float* hbuf = sm + WOFF + w * WFLO;      // [c=64][k stride 34]

    for (int e = t; e < D1 * D2; e += MTHR) W2s[e] = W2[e];
    for (int e = t; e < D2 * D3; e += MTHR) W3s[e] = W3[e];
    if (t < 192) w1s[t] = W1[t];
    if (t < D2) b2s[t] = b2[t];
    if (t < D3) b3s[t] = b3[t];
    __syncthreads();

    // phase-1 per-lane W1 slice for channels c = 2*lane, 2*lane+1
    const float w1x0 = w1s[2 * lane],       w1x1 = w1s[2 * lane + 1];
    const float w1y0 = w1s[64 + 2 * lane],  w1y1 = w1s[64 + 2 * lane + 1];
    const float w1z0 = w1s[128 + 2 * lane], w1z1 = w1s[128 + 2 * lane + 1];

    const int dg = lane & 7;                 // d-group: d = dg*8 .. dg*8+7
    const int kg = lane >> 3;                // k-group: k = kg*8 .. kg*8+7

    for (int cid = blockIdx.x * MW + w; cid < BB * SS; cid += MGRID * MW) {
        int b = cid >> 12;
        int s = cid & (SS - 1);
        const float4* ptsb = g_pts + b * NN;
        const float* F1b = g_F1 + (size_t)b * NN * D1;

        // ---- phase 1: cooperative gather + layer-1 -> hbuf[c][k] -----------
        {
            int id = g_idx[cid * KSAMP + lane];
            float4 p = ptsb[id];
            float4 cc = ptsb[s];
            float rx = p.x - cc.x, ry = p.y - cc.y, rz = p.z - cc.z;
#pragma unroll 4
            for (int k = 0; k < KSAMP; k++) {
                int   idk = __shfl_sync(0xffffffffu, id, k);
                float kx  = __shfl_sync(0xffffffffu, rx, k);
                float ky  = __shfl_sync(0xffffffffu, ry, k);
                float kz  = __shfl_sync(0xffffffffu, rz, k);
                float2 f = *(const float2*)&F1b[idk * D1 + 2 * lane];
                float v0 = fmaf(kz, w1z0, fmaf(ky, w1y0, fmaf(kx, w1x0, f.x)));
                float v1 = fmaf(kz, w1z1, fmaf(ky, w1y1, fmaf(kx, w1x1, f.y)));
                hbuf[(2 * lane) * HST + k]     = fmaxf(v0, 0.f);
                hbuf[(2 * lane + 1) * HST + k] = fmaxf(v1, 0.f);
            }
        }
        __syncwarp();

        // ---- phase 2: h2 = relu(h1 @ W2 + b2), 8k x 8d tile ----------------
        {
            u64 acc[4][8];
#pragma unroll
            for (int j = 0; j < 8; j++) {
                float bv = b2s[dg * 8 + j];
                u64 bp = pack2(bv, bv);
#pragma unroll
                for (int p = 0; p < 4; p++) acc[p][j] = bp;
            }
#pragma unroll 4
            for (int c = 0; c < D1; c++) {
                const u64* hr = (const u64*)&hbuf[c * HST + kg * 8];
                u64 h0 = hr[0], h1 = hr[1], h2 = hr[2], h3 = hr[3];
                const float4* wp = (const float4*)&W2s[c * D2 + dg * 8];
                float4 wa = wp[0], wb = wp[1];
                u64 w0 = pack2(wa.x, wa.x), w1 = pack2(wa.y, wa.y);
                u64 w2 = pack2(wa.z, wa.z), w3 = pack2(wa.w, wa.w);
                u64 w4 = pack2(wb.x, wb.x), w5 = pack2(wb.y, wb.y);
                u64 w6 = pack2(wb.z, wb.z), w7 = pack2(wb.w, wb.w);
                acc[0][0] = fma2(h0, w0, acc[0][0]); acc[0][1] = fma2(h0, w1, acc[0][1]);
                acc[0][2] = fma2(h0, w2, acc[0][2]); acc[0][3] = fma2(h0, w3, acc[0][3]);
                acc[0][4] = fma2(h0, w4, acc[0][4]); acc[0][5] = fma2(h0, w5, acc[0][5]);
                acc[0][6] = fma2(h0, w6, acc[0][6]); acc[0][7] = fma2(h0, w7, acc[0][7]);
                acc[1][0] = fma2(h1, w0, acc[1][0]); acc[1][1] = fma2(h1, w1, acc[1][1]);
                acc[1][2] = fma2(h1, w2, acc[1][2]); acc[1][3] = fma2(h1, w3, acc[1][3]);
                acc[1][4] = fma2(h1, w4, acc[1][4]); acc[1][5] = fma2(h1, w5, acc[1][5]);
                acc[1][6] = fma2(h1, w6, acc[1][6]); acc[1][7] = fma2(h1, w7, acc[1][7]);
                acc[2][0] = fma2(h2, w0, acc[2][0]); acc[2][1] = fma2(h2, w1, acc[2][1]);
                acc[2][2] = fma2(h2, w2, acc[2][2]); acc[2][3] = fma2(h2, w3, acc[2][3]);
                acc[2][4] = fma2(h2, w4, acc[2][4]); acc[2][5] = fma2(h2, w5, acc[2][5]);
                acc[2][6] = fma2(h2, w6, acc[2][6]); acc[2][7] = fma2(h2, w7, acc[2][7]);
                acc[3][0] = fma2(h3, w0, acc[3][0]); acc[3][1] = fma2(h3, w1, acc[3][1]);
                acc[3][2] = fma2(h3, w2, acc[3][2]); acc[3][3] = fma2(h3, w3, acc[3][3]);
                acc[3][4] = fma2(h3, w4, acc[3][4]); acc[3][5] = fma2(h3, w5, acc[3][5]);
                acc[3][6] = fma2(h3, w6, acc[3][6]); acc[3][7] = fma2(h3, w7, acc[3][7]);
            }
            __syncwarp();                    // all lanes done reading h1
            // write h2 transposed [d][k], relu applied
#pragma unroll
            for (int j = 0; j < 8; j++) {
#pragma unroll
                for (int p = 0; p < 4; p++) {
                    float lo, hi; unpack2(acc[p][j], lo, hi);
                    *(u64*)&hbuf[(dg * 8 + j) * HST + kg * 8 + 2 * p] =
                        pack2(fmaxf(lo, 0.f), fmaxf(hi, 0.f));
                }
            }
            __syncwarp();
        }

        // ---- phase 3: two 64-d halves of layer 3, max over k ---------------
#pragma unroll 1
        for (int half = 0; half < 2; half++) {
            u64 acc[4][8];
#pragma unroll
            for (int j = 0; j < 8; j++) {
                float bv = b3s[half * 64 + dg * 8 + j];
                u64 bp = pack2(bv, bv);
#pragma unroll
                for (int p = 0; p < 4; p++) acc[p][j] = bp;
            }
#pragma unroll 4
            for (int c = 0; c < D2; c++) {
                const u64* hr = (const u64*)&hbuf[c * HST + kg * 8];
                u64 h0 = hr[0], h1 = hr[1], h2 = hr[2], h3 = hr[3];
                const float4* wp = (const float4*)&W3s[c * D3 + half * 64 + dg * 8];
                float4 wa = wp[0], wb = wp[1];
                u64 w0 = pack2(wa.x, wa.x), w1 = pack2(wa.y, wa.y);
                u64 w2 = pack2(wa.z, wa.z), w3 = pack2(wa.w, wa.w);
                u64 w4 = pack2(wb.x, wb.x), w5 = pack2(wb.y, wb.y);
                u64 w6 = pack2(wb.z, wb.z), w7 = pack2(wb.w, wb.w);
                acc[0][0] = fma2(h0, w0, acc[0][0]); acc[0][1] = fma2(h0, w1, acc[0][1]);
                acc[0][2] = fma2(h0, w2, acc[0][2]); acc[0][3] = fma2(h0, w3, acc[0][3]);
                acc[0][4] = fma2(h0, w4, acc[0][4]); acc[0][5] = fma2(h0, w5, acc[0][5]);
                acc[0][6] = fma2(h0, w6, acc[0][6]); acc[0][7] = fma2(h0, w7, acc[0][7]);
                acc[1][0] = fma2(h1, w0, acc[1][0]); acc[1][1] = fma2(h1, w1, acc[1][1]);
                acc[1][2] = fma2(h1, w2, acc[1][2]); acc[1][3] = fma2(h1, w3, acc[1][3]);
                acc[1][4] = fma2(h1, w4, acc[1][4]); acc[1][5] = fma2(h1, w5, acc[1][5]);
                acc[1][6] = fma2(h1, w6, acc[1][6]); acc[1][7] = fma2(h1, w7, acc[1][7]);
                acc[2][0] = fma2(h2, w0, acc[2][0]); acc[2][1] = fma2(h2, w1, acc[2][1]);
                acc[2][2] = fma2(h2, w2, acc[2][2]); acc[2][3] = fma2(h2, w3, acc[2][3]);
                acc[2][4] = fma2(h2, w4, acc[2][4]); acc[2][5] = fma2(h2, w5, acc[2][5]);
                acc[2][6] = fma2(h2, w6, acc[2][6]); acc[2][7] = fma2(h2, w7, acc[2][7]);
                acc[3][0] = fma2(h3, w0, acc[3][0]); acc[3][1] = fma2(h3, w1, acc[3][1]);
                acc[3][2] = fma2(h3, w2, acc[3][2]); acc[3][3] = fma2(h3, w3, acc[3][3]);
                acc[3][4] = fma2(h3, w4, acc[3][4]); acc[3][5] = fma2(h3, w5, acc[3][5]);
                acc[3][6] = fma2(h3, w6, acc[3][6]); acc[3][7] = fma2(h3, w7, acc[3][7]);
            }
            // reduce: relu folded into max(0,.); cross k-groups via shfl
#pragma unroll
            for (int j = 0; j < 8; j++) {
                float m = 0.f;
#pragma unroll
                for (int p = 0; p < 4; p++) {
                    float lo, hi; unpack2(acc[p][j], lo, hi);
                    m = fmaxf(m, fmaxf(lo, hi));
                }
                m = fmaxf(m, __shfl_xor_sync(0xffffffffu, m, 8));
                m = fmaxf(m, __shfl_xor_sync(0xffffffffu, m, 16));
                if (kg == 0) {
                    int d = half * 64 + dg * 8 + j;
                    out[OUT_FEAT_BASE + (size_t)b * D3 * SS + (size_t)d * SS + s] = m;
                }
            }
        }
        __syncwarp();
    }
}

// ---------------------------------------------------------------------------
extern "C" void kernel_launch(void* const* d_in, const int* in_sizes, int n_in,
                              void* d_out, int out_size) {
    const float* xyz   = (const float*)d_in[0];
    const float* feats = (const float*)d_in[1];
    const float* W1    = (const float*)d_in[2];
    const float* b1    = (const float*)d_in[3];
    const float* W2    = (const float*)d_in[4];
    const float* b2    = (const float*)d_in[5];
    const float* W3    = (const float*)d_in[6];
    const float* b3    = (const float*)d_in[7];
    float* out = (float*)d_out;
    (void)in_sizes; (void)n_in; (void)out_size;

    cudaFuncSetAttribute(mlp_kernel, cudaFuncAttributeMaxDynamicSharedMemorySize, MLP_SMEM);

    prep_pts<<<(BB * NN + 255) / 256, 256>>>(xyz, out);
    prep_F1<<<BB * NN / 64, 256>>>(feats, W1, b1);
    ballq<<<BB * SS / 8, 256>>>();
    mlp_kernel<<<MGRID, MTHR, MLP_SMEM>>>(W1, W2, b2, W3, b3, out);
}

// round 10
// speedup vs baseline: 1.0628x; 1.0628x over previous
#include <cuda_runtime.h>

#define BB 2
#define NN 16384
#define SS 4096
#define KSAMP 32
#define CF 64
#define D1 64
#define D2 64
#define D3 128

typedef unsigned long long u64;

// scratch (__device__ globals per allocation rule)
__device__ __align__(16) float4 g_pts[BB * NN];   // x,y,z,|p|^2
__device__ __align__(16) float  g_px[BB * NN];
__device__ __align__(16) float  g_py[BB * NN];
__device__ __align__(16) float  g_pz[BB * NN];
__device__ __align__(16) float  g_F1[BB * NN * D1];
__device__ __align__(16) int    g_idx[BB * SS * KSAMP];

#define OUT_FEAT_BASE (BB * SS * 3)
#define OUT_SAMP_BASE (BB * SS * 3 + BB * D3 * SS)

// ---- packed f32x2 helpers -------------------------------------------------
__device__ __forceinline__ u64 fma2(u64 a, u64 b, u64 c) {
    u64 d;
    asm("fma.rn.f32x2 %0, %1, %2, %3;" : "=l"(d) : "l"(a), "l"(b), "l"(c));
    return d;
}
__device__ __forceinline__ u64 pack2(float lo, float hi) {
    u64 d;
    asm("mov.b64 %0, {%1, %2};" : "=l"(d) : "f"(lo), "f"(hi));
    return d;
}
__device__ __forceinline__ void unpack2(u64 v, float& lo, float& hi) {
    asm("mov.b64 {%0, %1}, %2;" : "=f"(lo), "=f"(hi) : "l"(v));
}

// ---------------------------------------------------------------------------
// fused: point prep (pts/px/py/pz/new_xyz/samp_idx) + F1 GEMM (mlp-style tile)
// grid = 128 blocks x 256 thr; block = 256 consecutive points of one batch.
#define PA_SMEM ((CF * D1 + D1 + 8 * CF * 34) * 4)

__global__ void __launch_bounds__(256) prep_all(
    const float* __restrict__ xyz, const float* __restrict__ feats,
    const float* __restrict__ W1, const float* __restrict__ b1,
    float* __restrict__ out) {
    extern __shared__ float sm[];
    float* Ws  = sm;                  // [cin=64][cout=64]
    float* b1s = Ws + CF * D1;        // 64
    int t = threadIdx.x, lane = t & 31, w = t >> 5;
    float* ftT = b1s + D1 + w * (CF * 34);   // per-warp [c=64][k stride 34]

    int b  = blockIdx.x >> 6;                // / (NN/256)
    int n0 = (blockIdx.x & 63) * 256;

    // stage W1 feat-part + b1
    for (int e = t; e < CF * D1; e += 256) Ws[e] = W1[(3 + e / D1) * D1 + (e % D1)];
    if (t < D1) b1s[t] = b1[t];

    // part A: point prep
    {
        int i = b * NN + n0 + t;
        float x = xyz[i * 3 + 0], y = xyz[i * 3 + 1], z = xyz[i * 3 + 2];
        float nn = x * x + y * y + z * z;
        g_pts[i] = make_float4(x, y, z, nn);
        g_px[i] = x; g_py[i] = y; g_pz[i] = z;
        int n = n0 + t;
        if (n < SS) {
            int o = (b * SS + n) * 3;
            out[o + 0] = x; out[o + 1] = y; out[o + 2] = z;
            out[OUT_SAMP_BASE + b * SS + n] = (float)n;
        }
    }
    __syncthreads();

    // part B: stage ft transposed [c][k] for this warp's 32 points (coalesced)
    int p0 = n0 + w * 32;                    // warp's first point
#pragma unroll 8
    for (int c = 0; c < CF; c++)
        ftT[c * 34 + lane] = feats[(b * CF + c) * NN + p0 + lane];
    __syncwarp();

    // GEMM: F1[pt][d] = b1[d] + sum_c ft[c][pt] * Ws[c][d], 8k x 8d tile
    const int dg = lane & 7, kg = lane >> 3;
    u64 acc[4][8];
#pragma unroll
    for (int j = 0; j < 8; j++) {
        float bv = b1s[dg * 8 + j];
        u64 bp = pack2(bv, bv);
#pragma unroll
        for (int p = 0; p < 4; p++) acc[p][j] = bp;
    }
#pragma unroll 4
    for (int c = 0; c < CF; c++) {
        const u64* hr = (const u64*)&ftT[c * 34 + kg * 8];
        u64 h0 = hr[0], h1 = hr[1], h2 = hr[2], h3 = hr[3];
        const float4* wp = (const float4*)&Ws[c * D1 + dg * 8];
        float4 wa = wp[0], wb = wp[1];
        u64 w0 = pack2(wa.x, wa.x), w1 = pack2(wa.y, wa.y);
        u64 w2 = pack2(wa.z, wa.z), w3 = pack2(wa.w, wa.w);
        u64 w4 = pack2(wb.x, wb.x), w5 = pack2(wb.y, wb.y);
        u64 w6 = pack2(wb.z, wb.z), w7 = pack2(wb.w, wb.w);
        acc[0][0] = fma2(h0, w0, acc[0][0]); acc[0][1] = fma2(h0, w1, acc[0][1]);
        acc[0][2] = fma2(h0, w2, acc[0][2]); acc[0][3] = fma2(h0, w3, acc[0][3]);
        acc[0][4] = fma2(h0, w4, acc[0][4]); acc[0][5] = fma2(h0, w5, acc[0][5]);
        acc[0][6] = fma2(h0, w6, acc[0][6]); acc[0][7] = fma2(h0, w7, acc[0][7]);
        acc[1][0] = fma2(h1, w0, acc[1][0]); acc[1][1] = fma2(h1, w1, acc[1][1]);
        acc[1][2] = fma2(h1, w2, acc[1][2]); acc[1][3] = fma2(h1, w3, acc[1][3]);
        acc[1][4] = fma2(h1, w4, acc[1][4]); acc[1][5] = fma2(h1, w5, acc[1][5]);
        acc[1][6] = fma2(h1, w6, acc[1][6]); acc[1][7] = fma2(h1, w7, acc[1][7]);
        acc[2][0] = fma2(h2, w0, acc[2][0]); acc[2][1] = fma2(h2, w1, acc[2][1]);
        acc[2][2] = fma2(h2, w2, acc[2][2]); acc[2][3] = fma2(h2, w3, acc[2][3]);
        acc[2][4] = fma2(h2, w4, acc[2][4]); acc[2][5] = fma2(h2, w5, acc[2][5]);
        acc[2][6] = fma2(h2, w6, acc[2][6]); acc[2][7] = fma2(h2, w7, acc[2][7]);
        acc[3][0] = fma2(h3, w0, acc[3][0]); acc[3][1] = fma2(h3, w1, acc[3][1]);
        acc[3][2] = fma2(h3, w2, acc[3][2]); acc[3][3] = fma2(h3, w3, acc[3][3]);
        acc[3][4] = fma2(h3, w4, acc[3][4]); acc[3][5] = fma2(h3, w5, acc[3][5]);
        acc[3][6] = fma2(h3, w6, acc[3][6]); acc[3][7] = fma2(h3, w7, acc[3][7]);
    }
    // store F1 (lo -> k=kg*8+2p, hi -> k+1)
    float* F1w = g_F1 + ((size_t)(b * NN + p0)) * D1;
#pragma unroll
    for (int p = 0; p < 4; p++) {
        int k = kg * 8 + 2 * p;
#pragma unroll
        for (int j = 0; j < 8; j++) {
            float lo, hi; unpack2(acc[p][j], lo, hi);
            int d = dg * 8 + j;
            F1w[(size_t)k * D1 + d]       = lo;
            F1w[(size_t)(k + 1) * D1 + d] = hi;
        }
    }
}

// ---------------------------------------------------------------------------
// ball query: 16 warps/block share 512-point smem tiles (halves L2 traffic).
__global__ void __launch_bounds__(512) ballq() {
    const float R2 = (float)(0.4 * 0.4);
    __shared__ float tx[512], ty[512], tz[512];
    int t = threadIdx.x;
    int lane = t & 31;
    int w = t >> 5;
    int cid = blockIdx.x * 16 + w;
    int b = cid / SS, s = cid % SS;
    const float* px = g_px + b * NN;
    const float* py = g_py + b * NN;
    const float* pz = g_pz + b * NN;

    float cx = px[s], cy = py[s], cz = pz[s];
    float cw = cx * cx + cy * cy + cz * cz;

    int cnt = 0, first = 0;
    for (int base = 0; base < NN; base += 512) {
        __syncthreads();
        tx[t] = px[base + t]; ty[t] = py[base + t]; tz[t] = pz[base + t];
        __syncthreads();
        if (cnt < KSAMP) {
#pragma unroll
            for (int j = 0; j < 16; j++) {
                int li = j * 32 + lane;
                float qx = tx[li], qy = ty[li], qz = tz[li];
                float dot = cx * qx + cy * qy + cz * qz;
                float qw = qx * qx + qy * qy + qz * qz;
                float d2 = (cw + qw) - 2.0f * dot;
                bool hit = d2 < R2;
                unsigned m = __ballot_sync(0xffffffffu, hit);
                if (m) {
                    if (cnt == 0) first = base + j * 32 + (__ffs(m) - 1);
                    int pos = cnt + __popc(m & ((1u << lane) - 1u));
                    if (hit && pos < KSAMP) g_idx[cid * KSAMP + pos] = base + j * 32 + lane;
                    cnt += __popc(m);
                    if (cnt >= KSAMP) break;
                }
            }
        }
        if (__syncthreads_and(cnt >= KSAMP)) break;
    }
    if (lane >= cnt) g_idx[cid * KSAMP + lane] = first;
}

// ---------------------------------------------------------------------------
// MLP (R7/v7): warp per centroid, 8k x 8d FFMA2 register tiles, transposed
// h[c][k] stride-34, broadcast weight LDS.128. MW=12 (best measured).
#define MW 12
#define MTHR 384
#define MGRID 148
#define HST 34
#define WFLO (D1 * HST)
#define WOFF (D1*D2 + D2*D3 + 3*64 + D2 + D3)
#define MLP_SMEM ((WOFF + MW * WFLO) * 4)

__global__ void __launch_bounds__(MTHR, 1) mlp_kernel(
    const float* __restrict__ W1, const float* __restrict__ W2,
    const float* __restrict__ b2, const float* __restrict__ W3,
    const float* __restrict__ b3, float* __restrict__ out) {
    extern __shared__ float sm[];
    float* W2s = sm;                         // 64*64, [c][d]
    float* W3s = W2s + D1 * D2;              // 64*128, [c][d]
    float* w1s = W3s + D2 * D3;              // 3*64
    float* b2s = w1s + 3 * 64;               // 64
    float* b3s = b2s + D2;                   // 128
    int t = threadIdx.x, lane = t & 31, w = t >> 5;
    float* hbuf = sm + WOFF + w * WFLO;      // [c=64][k stride 34]

    for (int e = t; e < D1 * D2; e += MTHR) W2s[e] = W2[e];
    for (int e = t; e < D2 * D3; e += MTHR) W3s[e] = W3[e];
    if (t < 192) w1s[t] = W1[t];
    if (t < D2) b2s[t] = b2[t];
    if (t < D3) b3s[t] = b3[t];
    __syncthreads();

    const float w1x0 = w1s[2 * lane],       w1x1 = w1s[2 * lane + 1];
    const float w1y0 = w1s[64 + 2 * lane],  w1y1 = w1s[64 + 2 * lane + 1];
    const float w1z0 = w1s[128 + 2 * lane], w1z1 = w1s[128 + 2 * lane + 1];

    const int dg = lane & 7;
    const int kg = lane >> 3;

    for (int cid = blockIdx.x * MW + w; cid < BB * SS; cid += MGRID * MW) {
        int b = cid >> 12;
        int s = cid & (SS - 1);
        const float4* ptsb = g_pts + b * NN;
        const float* F1b = g_F1 + (size_t)b * NN * D1;

        // ---- phase 1: cooperative gather + layer-1 -> hbuf[c][k] -----------
        {
            int id = g_idx[cid * KSAMP + lane];
            float4 p = ptsb[id];
            float4 cc = ptsb[s];
            float rx = p.x - cc.x, ry = p.y - cc.y, rz = p.z - cc.z;
#pragma unroll 4
            for (int k = 0; k < KSAMP; k++) {
                int   idk = __shfl_sync(0xffffffffu, id, k);
                float kx  = __shfl_sync(0xffffffffu, rx, k);
                float ky  = __shfl_sync(0xffffffffu, ry, k);
                float kz  = __shfl_sync(0xffffffffu, rz, k);
                float2 f = *(const float2*)&F1b[idk * D1 + 2 * lane];
                float v0 = fmaf(kz, w1z0, fmaf(ky, w1y0, fmaf(kx, w1x0, f.x)));
                float v1 = fmaf(kz, w1z1, fmaf(ky, w1y1, fmaf(kx, w1x1, f.y)));
                hbuf[(2 * lane) * HST + k]     = fmaxf(v0, 0.f);
                hbuf[(2 * lane + 1) * HST + k] = fmaxf(v1, 0.f);
            }
        }
        __syncwarp();

        // ---- phase 2: h2 = relu(h1 @ W2 + b2), 8k x 8d tile ----------------
        {
            u64 acc[4][8];
#pragma unroll
            for (int j = 0; j < 8; j++) {
                float bv = b2s[dg * 8 + j];
                u64 bp = pack2(bv, bv);
#pragma unroll
                for (int p = 0; p < 4; p++) acc[p][j] = bp;
            }
#pragma unroll 4
            for (int c = 0; c < D1; c++) {
                const u64* hr = (const u64*)&hbuf[c * HST + kg * 8];
                u64 h0 = hr[0], h1 = hr[1], h2 = hr[2], h3 = hr[3];
                const float4* wp = (const float4*)&W2s[c * D2 + dg * 8];
                float4 wa = wp[0], wb = wp[1];
                u64 w0 = pack2(wa.x, wa.x), w1 = pack2(wa.y, wa.y);
                u64 w2 = pack2(wa.z, wa.z), w3 = pack2(wa.w, wa.w);
                u64 w4 = pack2(wb.x, wb.x), w5 = pack2(wb.y, wb.y);
                u64 w6 = pack2(wb.z, wb.z), w7 = pack2(wb.w, wb.w);
                acc[0][0] = fma2(h0, w0, acc[0][0]); acc[0][1] = fma2(h0, w1, acc[0][1]);
                acc[0][2] = fma2(h0, w2, acc[0][2]); acc[0][3] = fma2(h0, w3, acc[0][3]);
                acc[0][4] = fma2(h0, w4, acc[0][4]); acc[0][5] = fma2(h0, w5, acc[0][5]);
                acc[0][6] = fma2(h0, w6, acc[0][6]); acc[0][7] = fma2(h0, w7, acc[0][7]);
                acc[1][0] = fma2(h1, w0, acc[1][0]); acc[1][1] = fma2(h1, w1, acc[1][1]);
                acc[1][2] = fma2(h1, w2, acc[1][2]); acc[1][3] = fma2(h1, w3, acc[1][3]);
                acc[1][4] = fma2(h1, w4, acc[1][4]); acc[1][5] = fma2(h1, w5, acc[1][5]);
                acc[1][6] = fma2(h1, w6, acc[1][6]); acc[1][7] = fma2(h1, w7, acc[1][7]);
                acc[2][0] = fma2(h2, w0, acc[2][0]); acc[2][1] = fma2(h2, w1, acc[2][1]);
                acc[2][2] = fma2(h2, w2, acc[2][2]); acc[2][3] = fma2(h2, w3, acc[2][3]);
                acc[2][4] = fma2(h2, w4, acc[2][4]); acc[2][5] = fma2(h2, w5, acc[2][5]);
                acc[2][6] = fma2(h2, w6, acc[2][6]); acc[2][7] = fma2(h2, w7, acc[2][7]);
                acc[3][0] = fma2(h3, w0, acc[3][0]); acc[3][1] = fma2(h3, w1, acc[3][1]);
                acc[3][2] = fma2(h3, w2, acc[3][2]); acc[3][3] = fma2(h3, w3, acc[3][3]);
                acc[3][4] = fma2(h3, w4, acc[3][4]); acc[3][5] = fma2(h3, w5, acc[3][5]);
                acc[3][6] = fma2(h3, w6, acc[3][6]); acc[3][7] = fma2(h3, w7, acc[3][7]);
            }
            __syncwarp();
#pragma unroll
            for (int j = 0; j < 8; j++) {
#pragma unroll
                for (int p = 0; p < 4; p++) {
                    float lo, hi; unpack2(acc[p][j], lo, hi);
                    *(u64*)&hbuf[(dg * 8 + j) * HST + kg * 8 + 2 * p] =
                        pack2(fmaxf(lo, 0.f), fmaxf(hi, 0.f));
                }
            }
            __syncwarp();
        }

        // ---- phase 3: two 64-d halves of layer 3, max over k ---------------
#pragma unroll 1
        for (int half = 0; half < 2; half++) {
            u64 acc[4][8];
#pragma unroll
            for (int j = 0; j < 8; j++) {
                float bv = b3s[half * 64 + dg * 8 + j];
                u64 bp = pack2(bv, bv);
#pragma unroll
                for (int p = 0; p < 4; p++) acc[p][j] = bp;
            }
#pragma unroll 4
            for (int c = 0; c < D2; c++) {
                const u64* hr = (const u64*)&hbuf[c * HST + kg * 8];
                u64 h0 = hr[0], h1 = hr[1], h2 = hr[2], h3 = hr[3];
                const float4* wp = (const float4*)&W3s[c * D3 + half * 64 + dg * 8];
                float4 wa = wp[0], wb = wp[1];
                u64 w0 = pack2(wa.x, wa.x), w1 = pack2(wa.y, wa.y);
                u64 w2 = pack2(wa.z, wa.z), w3 = pack2(wa.w, wa.w);
                u64 w4 = pack2(wb.x, wb.x), w5 = pack2(wb.y, wb.y);
                u64 w6 = pack2(wb.z, wb.z), w7 = pack2(wb.w, wb.w);
                acc[0][0] = fma2(h0, w0, acc[0][0]); acc[0][1] = fma2(h0, w1, acc[0][1]);
                acc[0][2] = fma2(h0, w2, acc[0][2]); acc[0][3] = fma2(h0, w3, acc[0][3]);
                acc[0][4] = fma2(h0, w4, acc[0][4]); acc[0][5] = fma2(h0, w5, acc[0][5]);
                acc[0][6] = fma2(h0, w6, acc[0][6]); acc[0][7] = fma2(h0, w7, acc[0][7]);
                acc[1][0] = fma2(h1, w0, acc[1][0]); acc[1][1] = fma2(h1, w1, acc[1][1]);
                acc[1][2] = fma2(h1, w2, acc[1][2]); acc[1][3] = fma2(h1, w3, acc[1][3]);
                acc[1][4] = fma2(h1, w4, acc[1][4]); acc[1][5] = fma2(h1, w5, acc[1][5]);
                acc[1][6] = fma2(h1, w6, acc[1][6]); acc[1][7] = fma2(h1, w7, acc[1][7]);
                acc[2][0] = fma2(h2, w0, acc[2][0]); acc[2][1] = fma2(h2, w1, acc[2][1]);
                acc[2][2] = fma2(h2, w2, acc[2][2]); acc[2][3] = fma2(h2, w3, acc[2][3]);
                acc[2][4] = fma2(h2, w4, acc[2][4]); acc[2][5] = fma2(h2, w5, acc[2][5]);
                acc[2][6] = fma2(h2, w6, acc[2][6]); acc[2][7] = fma2(h2, w7, acc[2][7]);
                acc[3][0] = fma2(h3, w0, acc[3][0]); acc[3][1] = fma2(h3, w1, acc[3][1]);
                acc[3][2] = fma2(h3, w2, acc[3][2]); acc[3][3] = fma2(h3, w3, acc[3][3]);
                acc[3][4] = fma2(h3, w4, acc[3][4]); acc[3][5] = fma2(h3, w5, acc[3][5]);
                acc[3][6] = fma2(h3, w6, acc[3][6]); acc[3][7] = fma2(h3, w7, acc[3][7]);
            }
#pragma unroll
            for (int j = 0; j < 8; j++) {
                float m = 0.f;
#pragma unroll
                for (int p = 0; p < 4; p++) {
                    float lo, hi; unpack2(acc[p][j], lo, hi);
                    m = fmaxf(m, fmaxf(lo, hi));
                }
                m = fmaxf(m, __shfl_xor_sync(0xffffffffu, m, 8));
                m = fmaxf(m, __shfl_xor_sync(0xffffffffu, m, 16));
                if (kg == 0) {
                    int d = half * 64 + dg * 8 + j;
                    out[OUT_FEAT_BASE + (size_t)b * D3 * SS + (size_t)d * SS + s] = m;
                }
            }
        }
        __syncwarp();
    }
}

// ---------------------------------------------------------------------------
extern "C" void kernel_launch(void* const* d_in, const int* in_sizes, int n_in,
                              void* d_out, int out_size) {
    const float* xyz   = (const float*)d_in[0];
    const float* feats = (const float*)d_in[1];
    const float* W1    = (const float*)d_in[2];
    const float* b1    = (const float*)d_in[3];
    const float* W2    = (const float*)d_in[4];
    const float* b2    = (const float*)d_in[5];
    const float* W3    = (const float*)d_in[6];
    const float* b3    = (const float*)d_in[7];
    float* out = (float*)d_out;
    (void)in_sizes; (void)n_in; (void)out_size;

    cudaFuncSetAttribute(prep_all, cudaFuncAttributeMaxDynamicSharedMemorySize, PA_SMEM);
    cudaFuncSetAttribute(mlp_kernel, cudaFuncAttributeMaxDynamicSharedMemorySize, MLP_SMEM);

    prep_all<<<BB * (NN / 256), 256, PA_SMEM>>>(xyz, feats, W1, b1, out);
    ballq<<<BB * SS / 16, 512>>>();
    mlp_kernel<<<MGRID, MTHR, MLP_SMEM>>>(W1, W2, b2, W3, b3, out);
}

// round 11
// speedup vs baseline: 1.0901x; 1.0257x over previous
#include <cuda_runtime.h>

#define BB 2
#define NN 16384
#define SS 4096
#define KSAMP 32
#define CF 64
#define D1 64
#define D2 64
#define D3 128

typedef unsigned long long u64;

// scratch (__device__ globals per allocation rule)
__device__ __align__(16) float4 g_pts[BB * NN];   // x,y,z,|p|^2
__device__ __align__(16) float  g_px[BB * NN];
__device__ __align__(16) float  g_py[BB * NN];
__device__ __align__(16) float  g_pz[BB * NN];
__device__ __align__(16) float  g_pw[BB * NN];
__device__ __align__(16) float  g_F1[BB * NN * D1];
__device__ __align__(16) int    g_idx[BB * SS * KSAMP];

#define OUT_FEAT_BASE (BB * SS * 3)
#define OUT_SAMP_BASE (BB * SS * 3 + BB * D3 * SS)

// ---- packed f32x2 helpers -------------------------------------------------
__device__ __forceinline__ u64 fma2(u64 a, u64 b, u64 c) {
    u64 d;
    asm("fma.rn.f32x2 %0, %1, %2, %3;" : "=l"(d) : "l"(a), "l"(b), "l"(c));
    return d;
}
__device__ __forceinline__ u64 pack2(float lo, float hi) {
    u64 d;
    asm("mov.b64 %0, {%1, %2};" : "=l"(d) : "f"(lo), "f"(hi));
    return d;
}
__device__ __forceinline__ void unpack2(u64 v, float& lo, float& hi) {
    asm("mov.b64 {%0, %1}, %2;" : "=f"(lo), "=f"(hi) : "l"(v));
}

// ---------------------------------------------------------------------------
// fused: point prep (pts/px/py/pz/pw/new_xyz/samp_idx) + F1 GEMM
#define PA_SMEM ((CF * D1 + D1 + 8 * CF * 34) * 4)

__global__ void __launch_bounds__(256) prep_all(
    const float* __restrict__ xyz, const float* __restrict__ feats,
    const float* __restrict__ W1, const float* __restrict__ b1,
    float* __restrict__ out) {
    extern __shared__ float sm[];
    float* Ws  = sm;                  // [cin=64][cout=64]
    float* b1s = Ws + CF * D1;        // 64
    int t = threadIdx.x, lane = t & 31, w = t >> 5;
    float* ftT = b1s + D1 + w * (CF * 34);   // per-warp [c=64][k stride 34]

    int b  = blockIdx.x >> 6;                // / (NN/256)
    int n0 = (blockIdx.x & 63) * 256;

    for (int e = t; e < CF * D1; e += 256) Ws[e] = W1[(3 + e / D1) * D1 + (e % D1)];
    if (t < D1) b1s[t] = b1[t];

    // part A: point prep
    {
        int i = b * NN + n0 + t;
        float x = xyz[i * 3 + 0], y = xyz[i * 3 + 1], z = xyz[i * 3 + 2];
        float nn = x * x + y * y + z * z;
        g_pts[i] = make_float4(x, y, z, nn);
        g_px[i] = x; g_py[i] = y; g_pz[i] = z; g_pw[i] = nn;
        int n = n0 + t;
        if (n < SS) {
            int o = (b * SS + n) * 3;
            out[o + 0] = x; out[o + 1] = y; out[o + 2] = z;
            out[OUT_SAMP_BASE + b * SS + n] = (float)n;
        }
    }
    __syncthreads();

    // part B: stage ft transposed [c][k] (coalesced)
    int p0 = n0 + w * 32;
#pragma unroll 8
    for (int c = 0; c < CF; c++)
        ftT[c * 34 + lane] = feats[(b * CF + c) * NN + p0 + lane];
    __syncwarp();

    const int dg = lane & 7, kg = lane >> 3;
    u64 acc[4][8];
#pragma unroll
    for (int j = 0; j < 8; j++) {
        float bv = b1s[dg * 8 + j];
        u64 bp = pack2(bv, bv);
#pragma unroll
        for (int p = 0; p < 4; p++) acc[p][j] = bp;
    }
#pragma unroll 4
    for (int c = 0; c < CF; c++) {
        const u64* hr = (const u64*)&ftT[c * 34 + kg * 8];
        u64 h0 = hr[0], h1 = hr[1], h2 = hr[2], h3 = hr[3];
        const float4* wp = (const float4*)&Ws[c * D1 + dg * 8];
        float4 wa = wp[0], wb = wp[1];
        u64 w0 = pack2(wa.x, wa.x), w1 = pack2(wa.y, wa.y);
        u64 w2 = pack2(wa.z, wa.z), w3 = pack2(wa.w, wa.w);
        u64 w4 = pack2(wb.x, wb.x), w5 = pack2(wb.y, wb.y);
        u64 w6 = pack2(wb.z, wb.z), w7 = pack2(wb.w, wb.w);
        acc[0][0] = fma2(h0, w0, acc[0][0]); acc[0][1] = fma2(h0, w1, acc[0][1]);
        acc[0][2] = fma2(h0, w2, acc[0][2]); acc[0][3] = fma2(h0, w3, acc[0][3]);
        acc[0][4] = fma2(h0, w4, acc[0][4]); acc[0][5] = fma2(h0, w5, acc[0][5]);
        acc[0][6] = fma2(h0, w6, acc[0][6]); acc[0][7] = fma2(h0, w7, acc[0][7]);
        acc[1][0] = fma2(h1, w0, acc[1][0]); acc[1][1] = fma2(h1, w1, acc[1][1]);
        acc[1][2] = fma2(h1, w2, acc[1][2]); acc[1][3] = fma2(h1, w3, acc[1][3]);
        acc[1][4] = fma2(h1, w4, acc[1][4]); acc[1][5] = fma2(h1, w5, acc[1][5]);
        acc[1][6] = fma2(h1, w6, acc[1][6]); acc[1][7] = fma2(h1, w7, acc[1][7]);
        acc[2][0] = fma2(h2, w0, acc[2][0]); acc[2][1] = fma2(h2, w1, acc[2][1]);
        acc[2][2] = fma2(h2, w2, acc[2][2]); acc[2][3] = fma2(h2, w3, acc[2][3]);
        acc[2][4] = fma2(h2, w4, acc[2][4]); acc[2][5] = fma2(h2, w5, acc[2][5]);
        acc[2][6] = fma2(h2, w6, acc[2][6]); acc[2][7] = fma2(h2, w7, acc[2][7]);
        acc[3][0] = fma2(h3, w0, acc[3][0]); acc[3][1] = fma2(h3, w1, acc[3][1]);
        acc[3][2] = fma2(h3, w2, acc[3][2]); acc[3][3] = fma2(h3, w3, acc[3][3]);
        acc[3][4] = fma2(h3, w4, acc[3][4]); acc[3][5] = fma2(h3, w5, acc[3][5]);
        acc[3][6] = fma2(h3, w6, acc[3][6]); acc[3][7] = fma2(h3, w7, acc[3][7]);
    }
    float* F1w = g_F1 + ((size_t)(b * NN + p0)) * D1;
#pragma unroll
    for (int p = 0; p < 4; p++) {
        int k = kg * 8 + 2 * p;
#pragma unroll
        for (int j = 0; j < 8; j++) {
            float lo, hi; unpack2(acc[p][j], lo, hi);
            int d = dg * 8 + j;
            F1w[(size_t)k * D1 + d]       = lo;
            F1w[(size_t)(k + 1) * D1 + d] = hi;
        }
    }
}

// ---------------------------------------------------------------------------
// ball query: 16 warps/block share 512-point smem tiles; |q|^2 staged too.
__global__ void __launch_bounds__(512) ballq() {
    const float R2 = (float)(0.4 * 0.4);
    __shared__ float tx[512], ty[512], tz[512], tw[512];
    int t = threadIdx.x;
    int lane = t & 31;
    int w = t >> 5;
    int cid = blockIdx.x * 16 + w;
    int b = cid / SS, s = cid % SS;
    const float* px = g_px + b * NN;
    const float* py = g_py + b * NN;
    const float* pz = g_pz + b * NN;
    const float* pw = g_pw + b * NN;

    float cx = px[s], cy = py[s], cz = pz[s];
    float cw = cx * cx + cy * cy + cz * cz;

    int cnt = 0, first = 0;
    for (int base = 0; base < NN; base += 512) {
        __syncthreads();
        tx[t] = px[base + t]; ty[t] = py[base + t]; tz[t] = pz[base + t];
        tw[t] = pw[base + t];
        __syncthreads();
        if (cnt < KSAMP) {
#pragma unroll
            for (int j = 0; j < 16; j++) {
                int li = j * 32 + lane;
                float qx = tx[li], qy = ty[li], qz = tz[li];
                float dot = cx * qx + cy * qy + cz * qz;
                float qw = tw[li];
                float d2 = (cw + qw) - 2.0f * dot;
                bool hit = d2 < R2;
                unsigned m = __ballot_sync(0xffffffffu, hit);
                if (m) {
                    if (cnt == 0) first = base + j * 32 + (__ffs(m) - 1);
                    int pos = cnt + __popc(m & ((1u << lane) - 1u));
                    if (hit && pos < KSAMP) g_idx[cid * KSAMP + pos] = base + j * 32 + lane;
                    cnt += __popc(m);
                    if (cnt >= KSAMP) break;
                }
            }
        }
        if (__syncthreads_and(cnt >= KSAMP)) break;
    }
    if (lane >= cnt) g_idx[cid * KSAMP + lane] = first;
}

// ---------------------------------------------------------------------------
// MLP v10: warp per centroid, 8k x 8d FFMA2 tiles; phase-1 gathers batch-
// prefetched (16 LDG.64 in flight) to kill the L2-latency hole.
#define MW 12
#define MTHR 384
#define MGRID 148
#define HST 34
#define WFLO (D1 * HST)
#define WOFF (D1*D2 + D2*D3 + 3*64 + D2 + D3)
#define MLP_SMEM ((WOFF + MW * WFLO) * 4)

__global__ void __launch_bounds__(MTHR, 1) mlp_kernel(
    const float* __restrict__ W1, const float* __restrict__ W2,
    const float* __restrict__ b2, const float* __restrict__ W3,
    const float* __restrict__ b3, float* __restrict__ out) {
    extern __shared__ float sm[];
    float* W2s = sm;                         // 64*64, [c][d]
    float* W3s = W2s + D1 * D2;              // 64*128, [c][d]
    float* w1s = W3s + D2 * D3;              // 3*64
    float* b2s = w1s + 3 * 64;               // 64
    float* b3s = b2s + D2;                   // 128
    int t = threadIdx.x, lane = t & 31, w = t >> 5;
    float* hbuf = sm + WOFF + w * WFLO;      // [c=64][k stride 34]

    for (int e = t; e < D1 * D2; e += MTHR) W2s[e] = W2[e];
    for (int e = t; e < D2 * D3; e += MTHR) W3s[e] = W3[e];
    if (t < 192) w1s[t] = W1[t];
    if (t < D2) b2s[t] = b2[t];
    if (t < D3) b3s[t] = b3[t];
    __syncthreads();

    const float w1x0 = w1s[2 * lane],       w1x1 = w1s[2 * lane + 1];
    const float w1y0 = w1s[64 + 2 * lane],  w1y1 = w1s[64 + 2 * lane + 1];
    const float w1z0 = w1s[128 + 2 * lane], w1z1 = w1s[128 + 2 * lane + 1];

    const int dg = lane & 7;
    const int kg = lane >> 3;

    for (int cid = blockIdx.x * MW + w; cid < BB * SS; cid += MGRID * MW) {
        int b = cid >> 12;
        int s = cid & (SS - 1);
        const float4* ptsb = g_pts + b * NN;
        const float* F1b = g_F1 + (size_t)b * NN * D1;

        // ---- phase 1: gather + layer-1 -> hbuf[c][k], batched prefetch -----
        {
            int id = g_idx[cid * KSAMP + lane];
            float4 p = ptsb[id];
            float4 cc = ptsb[s];
            float rx = p.x - cc.x, ry = p.y - cc.y, rz = p.z - cc.z;
#pragma unroll 1
            for (int hh = 0; hh < 2; hh++) {
                int kb = hh * 16;
                float2 fr[16];
#pragma unroll
                for (int k = 0; k < 16; k++) {
                    int idk = __shfl_sync(0xffffffffu, id, kb + k);
                    fr[k] = *(const float2*)&F1b[idk * D1 + 2 * lane];
                }
#pragma unroll
                for (int k = 0; k < 16; k++) {
                    float kx = __shfl_sync(0xffffffffu, rx, kb + k);
                    float ky = __shfl_sync(0xffffffffu, ry, kb + k);
                    float kz = __shfl_sync(0xffffffffu, rz, kb + k);
                    float v0 = fmaf(kz, w1z0, fmaf(ky, w1y0, fmaf(kx, w1x0, fr[k].x)));
                    float v1 = fmaf(kz, w1z1, fmaf(ky, w1y1, fmaf(kx, w1x1, fr[k].y)));
                    hbuf[(2 * lane) * HST + kb + k]     = fmaxf(v0, 0.f);
                    hbuf[(2 * lane + 1) * HST + kb + k] = fmaxf(v1, 0.f);
                }
            }
        }
        __syncwarp();

        // ---- phase 2: h2 = relu(h1 @ W2 + b2), 8k x 8d tile ----------------
        {
            u64 acc[4][8];
#pragma unroll
            for (int j = 0; j < 8; j++) {
                float bv = b2s[dg * 8 + j];
                u64 bp = pack2(bv, bv);
#pragma unroll
                for (int p = 0; p < 4; p++) acc[p][j] = bp;
            }
#pragma unroll 4
            for (int c = 0; c < D1; c++) {
                const u64* hr = (const u64*)&hbuf[c * HST + kg * 8];
                u64 h0 = hr[0], h1 = hr[1], h2 = hr[2], h3 = hr[3];
                const float4* wp = (const float4*)&W2s[c * D2 + dg * 8];
                float4 wa = wp[0], wb = wp[1];
                u64 w0 = pack2(wa.x, wa.x), w1 = pack2(wa.y, wa.y);
                u64 w2 = pack2(wa.z, wa.z), w3 = pack2(wa.w, wa.w);
                u64 w4 = pack2(wb.x, wb.x), w5 = pack2(wb.y, wb.y);
                u64 w6 = pack2(wb.z, wb.z), w7 = pack2(wb.w, wb.w);
                acc[0][0] = fma2(h0, w0, acc[0][0]); acc[0][1] = fma2(h0, w1, acc[0][1]);
                acc[0][2] = fma2(h0, w2, acc[0][2]); acc[0][3] = fma2(h0, w3, acc[0][3]);
                acc[0][4] = fma2(h0, w4, acc[0][4]); acc[0][5] = fma2(h0, w5, acc[0][5]);
                acc[0][6] = fma2(h0, w6, acc[0][6]); acc[0][7] = fma2(h0, w7, acc[0][7]);
                acc[1][0] = fma2(h1, w0, acc[1][0]); acc[1][1] = fma2(h1, w1, acc[1][1]);
                acc[1][2] = fma2(h1, w2, acc[1][2]); acc[1][3] = fma2(h1, w3, acc[1][3]);
                acc[1][4] = fma2(h1, w4, acc[1][4]); acc[1][5] = fma2(h1, w5, acc[1][5]);
                acc[1][6] = fma2(h1, w6, acc[1][6]); acc[1][7] = fma2(h1, w7, acc[1][7]);
                acc[2][0] = fma2(h2, w0, acc[2][0]); acc[2][1] = fma2(h2, w1, acc[2][1]);
                acc[2][2] = fma2(h2, w2, acc[2][2]); acc[2][3] = fma2(h2, w3, acc[2][3]);
                acc[2][4] = fma2(h2, w4, acc[2][4]); acc[2][5] = fma2(h2, w5, acc[2][5]);
                acc[2][6] = fma2(h2, w6, acc[2][6]); acc[2][7] = fma2(h2, w7, acc[2][7]);
                acc[3][0] = fma2(h3, w0, acc[3][0]); acc[3][1] = fma2(h3, w1, acc[3][1]);
                acc[3][2] = fma2(h3, w2, acc[3][2]); acc[3][3] = fma2(h3, w3, acc[3][3]);
                acc[3][4] = fma2(h3, w4, acc[3][4]); acc[3][5] = fma2(h3, w5, acc[3][5]);
                acc[3][6] = fma2(h3, w6, acc[3][6]); acc[3][7] = fma2(h3, w7, acc[3][7]);
            }
            __syncwarp();
#pragma unroll
            for (int j = 0; j < 8; j++) {
#pragma unroll
                for (int p = 0; p < 4; p++) {
                    float lo, hi; unpack2(acc[p][j], lo, hi);
                    *(u64*)&hbuf[(dg * 8 + j) * HST + kg * 8 + 2 * p] =
                        pack2(fmaxf(lo, 0.f), fmaxf(hi, 0.f));
                }
            }
            __syncwarp();
        }

        // ---- phase 3: two 64-d halves of layer 3, max over k ---------------
#pragma unroll 1
        for (int half = 0; half < 2; half++) {
            u64 acc[4][8];
#pragma unroll
            for (int j = 0; j < 8; j++) {
                float bv = b3s[half * 64 + dg * 8 + j];
                u64 bp = pack2(bv, bv);
#pragma unroll
                for (int p = 0; p < 4; p++) acc[p][j] = bp;
            }
#pragma unroll 4
            for (int c = 0; c < D2; c++) {
                const u64* hr = (const u64*)&hbuf[c * HST + kg * 8];
                u64 h0 = hr[0], h1 = hr[1], h2 = hr[2], h3 = hr[3];
                const float4* wp = (const float4*)&W3s[c * D3 + half * 64 + dg * 8];
                float4 wa = wp[0], wb = wp[1];
                u64 w0 = pack2(wa.x, wa.x), w1 = pack2(wa.y, wa.y);
                u64 w2 = pack2(wa.z, wa.z), w3 = pack2(wa.w, wa.w);
                u64 w4 = pack2(wb.x, wb.x), w5 = pack2(wb.y, wb.y);
                u64 w6 = pack2(wb.z, wb.z), w7 = pack2(wb.w, wb.w);
                acc[0][0] = fma2(h0, w0, acc[0][0]); acc[0][1] = fma2(h0, w1, acc[0][1]);
                acc[0][2] = fma2(h0, w2, acc[0][2]); acc[0][3] = fma2(h0, w3, acc[0][3]);
                acc[0][4] = fma2(h0, w4, acc[0][4]); acc[0][5] = fma2(h0, w5, acc[0][5]);
                acc[0][6] = fma2(h0, w6, acc[0][6]); acc[0][7] = fma2(h0, w7, acc[0][7]);
                acc[1][0] = fma2(h1, w0, acc[1][0]); acc[1][1] = fma2(h1, w1, acc[1][1]);
                acc[1][2] = fma2(h1, w2, acc[1][2]); acc[1][3] = fma2(h1, w3, acc[1][3]);
                acc[1][4] = fma2(h1, w4, acc[1][4]); acc[1][5] = fma2(h1, w5, acc[1][5]);
                acc[1][6] = fma2(h1, w6, acc[1][6]); acc[1][7] = fma2(h1, w7, acc[1][7]);
                acc[2][0] = fma2(h2, w0, acc[2][0]); acc[2][1] = fma2(h2, w1, acc[2][1]);
                acc[2][2] = fma2(h2, w2, acc[2][2]); acc[2][3] = fma2(h2, w3, acc[2][3]);
                acc[2][4] = fma2(h2, w4, acc[2][4]); acc[2][5] = fma2(h2, w5, acc[2][5]);
                acc[2][6] = fma2(h2, w6, acc[2][6]); acc[2][7] = fma2(h2, w7, acc[2][7]);
                acc[3][0] = fma2(h3, w0, acc[3][0]); acc[3][1] = fma2(h3, w1, acc[3][1]);
                acc[3][2] = fma2(h3, w2, acc[3][2]); acc[3][3] = fma2(h3, w3, acc[3][3]);
                acc[3][4] = fma2(h3, w4, acc[3][4]); acc[3][5] = fma2(h3, w5, acc[3][5]);
                acc[3][6] = fma2(h3, w6, acc[3][6]); acc[3][7] = fma2(h3, w7, acc[3][7]);
            }
#pragma unroll
            for (int j = 0; j < 8; j++) {
                float m = 0.f;
#pragma unroll
                for (int p = 0; p < 4; p++) {
                    float lo, hi; unpack2(acc[p][j], lo, hi);
                    m = fmaxf(m, fmaxf(lo, hi));
                }
                m = fmaxf(m, __shfl_xor_sync(0xffffffffu, m, 8));
                m = fmaxf(m, __shfl_xor_sync(0xffffffffu, m, 16));
                if (kg == 0) {
                    int d = half * 64 + dg * 8 + j;
                    out[OUT_FEAT_BASE + (size_t)b * D3 * SS + (size_t)d * SS + s] = m;
                }
            }
        }
        __syncwarp();
    }
}

// ---------------------------------------------------------------------------
extern "C" void kernel_launch(void* const* d_in, const int* in_sizes, int n_in,
                              void* d_out, int out_size) {
    const float* xyz   = (const float*)d_in[0];
    const float* feats = (const float*)d_in[1];
    const float* W1    = (const float*)d_in[2];
    const float* b1    = (const float*)d_in[3];
    const float* W2    = (const float*)d_in[4];
    const float* b2    = (const float*)d_in[5];
    const float* W3    = (const float*)d_in[6];
    const float* b3    = (const float*)d_in[7];
    float* out = (float*)d_out;
    (void)in_sizes; (void)n_in; (void)out_size;

    cudaFuncSetAttribute(prep_all, cudaFuncAttributeMaxDynamicSharedMemorySize, PA_SMEM);
    cudaFuncSetAttribute(mlp_kernel, cudaFuncAttributeMaxDynamicSharedMemorySize, MLP_SMEM);

    prep_all<<<BB * (NN / 256), 256, PA_SMEM>>>(xyz, feats, W1, b1, out);
    ballq<<<BB * SS / 16, 512>>>();
    mlp_kernel<<<MGRID, MTHR, MLP_SMEM>>>(W1, W2, b2, W3, b3, out);
}

// round 12
// speedup vs baseline: 1.1490x; 1.0540x over previous
#include <cuda_runtime.h>

#define BB 2
#define NN 16384
#define SS 4096
#define KSAMP 32
#define CF 64
#define D1 64
#define D2 64
#define D3 128

typedef unsigned long long u64;

// scratch (__device__ globals per allocation rule)
__device__ __align__(16) float4 g_pts[BB * NN];   // x,y,z,|p|^2
__device__ __align__(16) float  g_F1[BB * NN * D1];
__device__ __align__(16) int    g_idx[BB * SS * KSAMP];

#define OUT_FEAT_BASE (BB * SS * 3)
#define OUT_SAMP_BASE (BB * SS * 3 + BB * D3 * SS)

// ---- packed f32x2 helpers -------------------------------------------------
__device__ __forceinline__ u64 fma2(u64 a, u64 b, u64 c) {
    u64 d;
    asm("fma.rn.f32x2 %0, %1, %2, %3;" : "=l"(d) : "l"(a), "l"(b), "l"(c));
    return d;
}
__device__ __forceinline__ u64 pack2(float lo, float hi) {
    u64 d;
    asm("mov.b64 %0, {%1, %2};" : "=l"(d) : "f"(lo), "f"(hi));
    return d;
}
__device__ __forceinline__ void unpack2(u64 v, float& lo, float& hi) {
    asm("mov.b64 {%0, %1}, %2;" : "=f"(lo), "=f"(hi) : "l"(v));
}

// ---------------------------------------------------------------------------
// fused: point prep (pts/new_xyz/samp_idx) + F1 GEMM
#define PA_SMEM ((CF * D1 + D1 + 8 * CF * 34) * 4)

__global__ void __launch_bounds__(256) prep_all(
    const float* __restrict__ xyz, const float* __restrict__ feats,
    const float* __restrict__ W1, const float* __restrict__ b1,
    float* __restrict__ out) {
    extern __shared__ float sm[];
    float* Ws  = sm;                  // [cin=64][cout=64]
    float* b1s = Ws + CF * D1;        // 64
    int t = threadIdx.x, lane = t & 31, w = t >> 5;
    float* ftT = b1s + D1 + w * (CF * 34);   // per-warp [c=64][k stride 34]

    int b  = blockIdx.x >> 6;                // / (NN/256)
    int n0 = (blockIdx.x & 63) * 256;

    for (int e = t; e < CF * D1; e += 256) Ws[e] = W1[(3 + e / D1) * D1 + (e % D1)];
    if (t < D1) b1s[t] = b1[t];

    // part A: point prep
    {
        int i = b * NN + n0 + t;
        float x = xyz[i * 3 + 0], y = xyz[i * 3 + 1], z = xyz[i * 3 + 2];
        float nn = x * x + y * y + z * z;
        g_pts[i] = make_float4(x, y, z, nn);
        int n = n0 + t;
        if (n < SS) {
            int o = (b * SS + n) * 3;
            out[o + 0] = x; out[o + 1] = y; out[o + 2] = z;
            out[OUT_SAMP_BASE + b * SS + n] = (float)n;
        }
    }
    __syncthreads();

    // part B: stage ft transposed [c][k] (coalesced)
    int p0 = n0 + w * 32;
#pragma unroll 8
    for (int c = 0; c < CF; c++)
        ftT[c * 34 + lane] = feats[(b * CF + c) * NN + p0 + lane];
    __syncwarp();

    const int dg = lane & 7, kg = lane >> 3;
    u64 acc[4][8];
#pragma unroll
    for (int j = 0; j < 8; j++) {
        float bv = b1s[dg * 8 + j];
        u64 bp = pack2(bv, bv);
#pragma unroll
        for (int p = 0; p < 4; p++) acc[p][j] = bp;
    }
#pragma unroll 4
    for (int c = 0; c < CF; c++) {
        const u64* hr = (const u64*)&ftT[c * 34 + kg * 8];
        u64 h0 = hr[0], h1 = hr[1], h2 = hr[2], h3 = hr[3];
        const float4* wp = (const float4*)&Ws[c * D1 + dg * 8];
        float4 wa = wp[0], wb = wp[1];
        u64 w0 = pack2(wa.x, wa.x), w1 = pack2(wa.y, wa.y);
        u64 w2 = pack2(wa.z, wa.z), w3 = pack2(wa.w, wa.w);
        u64 w4 = pack2(wb.x, wb.x), w5 = pack2(wb.y, wb.y);
        u64 w6 = pack2(wb.z, wb.z), w7 = pack2(wb.w, wb.w);
        acc[0][0] = fma2(h0, w0, acc[0][0]); acc[0][1] = fma2(h0, w1, acc[0][1]);
        acc[0][2] = fma2(h0, w2, acc[0][2]); acc[0][3] = fma2(h0, w3, acc[0][3]);
        acc[0][4] = fma2(h0, w4, acc[0][4]); acc[0][5] = fma2(h0, w5, acc[0][5]);
        acc[0][6] = fma2(h0, w6, acc[0][6]); acc[0][7] = fma2(h0, w7, acc[0][7]);
        acc[1][0] = fma2(h1, w0, acc[1][0]); acc[1][1] = fma2(h1, w1, acc[1][1]);
        acc[1][2] = fma2(h1, w2, acc[1][2]); acc[1][3] = fma2(h1, w3, acc[1][3]);
        acc[1][4] = fma2(h1, w4, acc[1][4]); acc[1][5] = fma2(h1, w5, acc[1][5]);
        acc[1][6] = fma2(h1, w6, acc[1][6]); acc[1][7] = fma2(h1, w7, acc[1][7]);
        acc[2][0] = fma2(h2, w0, acc[2][0]); acc[2][1] = fma2(h2, w1, acc[2][1]);
        acc[2][2] = fma2(h2, w2, acc[2][2]); acc[2][3] = fma2(h2, w3, acc[2][3]);
        acc[2][4] = fma2(h2, w4, acc[2][4]); acc[2][5] = fma2(h2, w5, acc[2][5]);
        acc[2][6] = fma2(h2, w6, acc[2][6]); acc[2][7] = fma2(h2, w7, acc[2][7]);
        acc[3][0] = fma2(h3, w0, acc[3][0]); acc[3][1] = fma2(h3, w1, acc[3][1]);
        acc[3][2] = fma2(h3, w2, acc[3][2]); acc[3][3] = fma2(h3, w3, acc[3][3]);
        acc[3][4] = fma2(h3, w4, acc[3][4]); acc[3][5] = fma2(h3, w5, acc[3][5]);
        acc[3][6] = fma2(h3, w6, acc[3][6]); acc[3][7] = fma2(h3, w7, acc[3][7]);
    }
    float* F1w = g_F1 + ((size_t)(b * NN + p0)) * D1;
#pragma unroll
    for (int p = 0; p < 4; p++) {
        int k = kg * 8 + 2 * p;
#pragma unroll
        for (int j = 0; j < 8; j++) {
            float lo, hi; unpack2(acc[p][j], lo, hi);
            int d = dg * 8 + j;
            F1w[(size_t)k * D1 + d]       = lo;
            F1w[(size_t)(k + 1) * D1 + d] = hi;
        }
    }
}

// ---------------------------------------------------------------------------
// ball query: 16 warps/block share 512-point float4 smem tiles (1 LDS.128
// per 32-pt test group instead of 4 scalar LDS). Same d2 expression ->
// bit-identical hit decisions.
__global__ void __launch_bounds__(512) ballq() {
    const float R2 = (float)(0.4 * 0.4);
    __shared__ float4 tq[512];
    int t = threadIdx.x;
    int lane = t & 31;
    int w = t >> 5;
    int cid = blockIdx.x * 16 + w;
    int b = cid / SS, s = cid % SS;
    const float4* pts = g_pts + b * NN;

    float4 cc = pts[s];
    float cx = cc.x, cy = cc.y, cz = cc.z, cw = cc.w;

    int cnt = 0, first = 0;
    for (int base = 0; base < NN; base += 512) {
        __syncthreads();
        tq[t] = pts[base + t];
        __syncthreads();
        if (cnt < KSAMP) {
#pragma unroll
            for (int j = 0; j < 16; j++) {
                float4 q = tq[j * 32 + lane];
                float dot = cx * q.x + cy * q.y + cz * q.z;
                float d2 = (cw + q.w) - 2.0f * dot;
                bool hit = d2 < R2;
                unsigned m = __ballot_sync(0xffffffffu, hit);
                if (m) {
                    if (cnt == 0) first = base + j * 32 + (__ffs(m) - 1);
                    int pos = cnt + __popc(m & ((1u << lane) - 1u));
                    if (hit && pos < KSAMP) g_idx[cid * KSAMP + pos] = base + j * 32 + lane;
                    cnt += __popc(m);
                    if (cnt >= KSAMP) break;
                }
            }
        }
        if (__syncthreads_and(cnt >= KSAMP)) break;
    }
    if (lane >= cnt) g_idx[cid * KSAMP + lane] = first;
}

// ---------------------------------------------------------------------------
// MLP v10 (unchanged): warp per centroid, 8k x 8d FFMA2 tiles; phase-1
// gathers batch-prefetched (16 LDG.64 in flight).
#define MW 12
#define MTHR 384
#define MGRID 148
#define HST 34
#define WFLO (D1 * HST)
#define WOFF (D1*D2 + D2*D3 + 3*64 + D2 + D3)
#define MLP_SMEM ((WOFF + MW * WFLO) * 4)

__global__ void __launch_bounds__(MTHR, 1) mlp_kernel(
    const float* __restrict__ W1, const float* __restrict__ W2,
    const float* __restrict__ b2, const float* __restrict__ W3,
    const float* __restrict__ b3, float* __restrict__ out) {
    extern __shared__ float sm[];
    float* W2s = sm;                         // 64*64, [c][d]
    float* W3s = W2s + D1 * D2;              // 64*128, [c][d]
    float* w1s = W3s + D2 * D3;              // 3*64
    float* b2s = w1s + 3 * 64;               // 64
    float* b3s = b2s + D2;                   // 128
    int t = threadIdx.x, lane = t & 31, w = t >> 5;
    float* hbuf = sm + WOFF + w * WFLO;      // [c=64][k stride 34]

    for (int e = t; e < D1 * D2; e += MTHR) W2s[e] = W2[e];
    for (int e = t; e < D2 * D3; e += MTHR) W3s[e] = W3[e];
    if (t < 192) w1s[t] = W1[t];
    if (t < D2) b2s[t] = b2[t];
    if (t < D3) b3s[t] = b3[t];
    __syncthreads();

    const float w1x0 = w1s[2 * lane],       w1x1 = w1s[2 * lane + 1];
    const float w1y0 = w1s[64 + 2 * lane],  w1y1 = w1s[64 + 2 * lane + 1];
    const float w1z0 = w1s[128 + 2 * lane], w1z1 = w1s[128 + 2 * lane + 1];

    const int dg = lane & 7;
    const int kg = lane >> 3;

    for (int cid = blockIdx.x * MW + w; cid < BB * SS; cid += MGRID * MW) {
        int b = cid >> 12;
        int s = cid & (SS - 1);
        const float4* ptsb = g_pts + b * NN;
        const float* F1b = g_F1 + (size_t)b * NN * D1;

        // ---- phase 1: gather + layer-1 -> hbuf[c][k], batched prefetch -----
        {
            int id = g_idx[cid * KSAMP + lane];
            float4 p = ptsb[id];
            float4 cc = ptsb[s];
            float rx = p.x - cc.x, ry = p.y - cc.y, rz = p.z - cc.z;
#pragma unroll 1
            for (int hh = 0; hh < 2; hh++) {
                int kb = hh * 16;
                float2 fr[16];
#pragma unroll
                for (int k = 0; k < 16; k++) {
                    int idk = __shfl_sync(0xffffffffu, id, kb + k);
                    fr[k] = *(const float2*)&F1b[idk * D1 + 2 * lane];
                }
#pragma unroll
                for (int k = 0; k < 16; k++) {
                    float kx = __shfl_sync(0xffffffffu, rx, kb + k);
                    float ky = __shfl_sync(0xffffffffu, ry, kb + k);
                    float kz = __shfl_sync(0xffffffffu, rz, kb + k);
                    float v0 = fmaf(kz, w1z0, fmaf(ky, w1y0, fmaf(kx, w1x0, fr[k].x)));
                    float v1 = fmaf(kz, w1z1, fmaf(ky, w1y1, fmaf(kx, w1x1, fr[k].y)));
                    hbuf[(2 * lane) * HST + kb + k]     = fmaxf(v0, 0.f);
                    hbuf[(2 * lane + 1) * HST + kb + k] = fmaxf(v1, 0.f);
                }
            }
        }
        __syncwarp();

        // ---- phase 2: h2 = relu(h1 @ W2 + b2), 8k x 8d tile ----------------
        {
            u64 acc[4][8];
#pragma unroll
            for (int j = 0; j < 8; j++) {
                float bv = b2s[dg * 8 + j];
                u64 bp = pack2(bv, bv);
#pragma unroll
                for (int p = 0; p < 4; p++) acc[p][j] = bp;
            }
#pragma unroll 4
            for (int c = 0; c < D1; c++) {
                const u64* hr = (const u64*)&hbuf[c * HST + kg * 8];
                u64 h0 = hr[0], h1 = hr[1], h2 = hr[2], h3 = hr[3];
                const float4* wp = (const float4*)&W2s[c * D2 + dg * 8];
                float4 wa = wp[0], wb = wp[1];
                u64 w0 = pack2(wa.x, wa.x), w1 = pack2(wa.y, wa.y);
                u64 w2 = pack2(wa.z, wa.z), w3 = pack2(wa.w, wa.w);
                u64 w4 = pack2(wb.x, wb.x), w5 = pack2(wb.y, wb.y);
                u64 w6 = pack2(wb.z, wb.z), w7 = pack2(wb.w, wb.w);
                acc[0][0] = fma2(h0, w0, acc[0][0]); acc[0][1] = fma2(h0, w1, acc[0][1]);
                acc[0][2] = fma2(h0, w2, acc[0][2]); acc[0][3] = fma2(h0, w3, acc[0][3]);
                acc[0][4] = fma2(h0, w4, acc[0][4]); acc[0][5] = fma2(h0, w5, acc[0][5]);
                acc[0][6] = fma2(h0, w6, acc[0][6]); acc[0][7] = fma2(h0, w7, acc[0][7]);
                acc[1][0] = fma2(h1, w0, acc[1][0]); acc[1][1] = fma2(h1, w1, acc[1][1]);
                acc[1][2] = fma2(h1, w2, acc[1][2]); acc[1][3] = fma2(h1, w3, acc[1][3]);
                acc[1][4] = fma2(h1, w4, acc[1][4]); acc[1][5] = fma2(h1, w5, acc[1][5]);
                acc[1][6] = fma2(h1, w6, acc[1][6]); acc[1][7] = fma2(h1, w7, acc[1][7]);
                acc[2][0] = fma2(h2, w0, acc[2][0]); acc[2][1] = fma2(h2, w1, acc[2][1]);
                acc[2][2] = fma2(h2, w2, acc[2][2]); acc[2][3] = fma2(h2, w3, acc[2][3]);
                acc[2][4] = fma2(h2, w4, acc[2][4]); acc[2][5] = fma2(h2, w5, acc[2][5]);
                acc[2][6] = fma2(h2, w6, acc[2][6]); acc[2][7] = fma2(h2, w7, acc[2][7]);
                acc[3][0] = fma2(h3, w0, acc[3][0]); acc[3][1] = fma2(h3, w1, acc[3][1]);
                acc[3][2] = fma2(h3, w2, acc[3][2]); acc[3][3] = fma2(h3, w3, acc[3][3]);
                acc[3][4] = fma2(h3, w4, acc[3][4]); acc[3][5] = fma2(h3, w5, acc[3][5]);
                acc[3][6] = fma2(h3, w6, acc[3][6]); acc[3][7] = fma2(h3, w7, acc[3][7]);
            }
            __syncwarp();
#pragma unroll
            for (int j = 0; j < 8; j++) {
#pragma unroll
                for (int p = 0; p < 4; p++) {
                    float lo, hi; unpack2(acc[p][j], lo, hi);
                    *(u64*)&hbuf[(dg * 8 + j) * HST + kg * 8 + 2 * p] =
                        pack2(fmaxf(lo, 0.f), fmaxf(hi, 0.f));
                }
            }
            __syncwarp();
        }

        // ---- phase 3: two 64-d halves of layer 3, max over k ---------------
#pragma unroll 1
        for (int half = 0; half < 2; half++) {
            u64 acc[4][8];
#pragma unroll
            for (int j = 0; j < 8; j++) {
                float bv = b3s[half * 64 + dg * 8 + j];
                u64 bp = pack2(bv, bv);
#pragma unroll
                for (int p = 0; p < 4; p++) acc[p][j] = bp;
            }
#pragma unroll 4
            for (int c = 0; c < D2; c++) {
                const u64* hr = (const u64*)&hbuf[c * HST + kg * 8];
                u64 h0 = hr[0], h1 = hr[1], h2 = hr[2], h3 = hr[3];
                const float4* wp = (const float4*)&W3s[c * D3 + half * 64 + dg * 8];
                float4 wa = wp[0], wb = wp[1];
                u64 w0 = pack2(wa.x, wa.x), w1 = pack2(wa.y, wa.y);
                u64 w2 = pack2(wa.z, wa.z), w3 = pack2(wa.w, wa.w);
                u64 w4 = pack2(wb.x, wb.x), w5 = pack2(wb.y, wb.y);
                u64 w6 = pack2(wb.z, wb.z), w7 = pack2(wb.w, wb.w);
                acc[0][0] = fma2(h0, w0, acc[0][0]); acc[0][1] = fma2(h0, w1, acc[0][1]);
                acc[0][2] = fma2(h0, w2, acc[0][2]); acc[0][3] = fma2(h0, w3, acc[0][3]);
                acc[0][4] = fma2(h0, w4, acc[0][4]); acc[0][5] = fma2(h0, w5, acc[0][5]);
                acc[0][6] = fma2(h0, w6, acc[0][6]); acc[0][7] = fma2(h0, w7, acc[0][7]);
                acc[1][0] = fma2(h1, w0, acc[1][0]); acc[1][1] = fma2(h1, w1, acc[1][1]);
                acc[1][2] = fma2(h1, w2, acc[1][2]); acc[1][3] = fma2(h1, w3, acc[1][3]);
                acc[1][4] = fma2(h1, w4, acc[1][4]); acc[1][5] = fma2(h1, w5, acc[1][5]);
                acc[1][6] = fma2(h1, w6, acc[1][6]); acc[1][7] = fma2(h1, w7, acc[1][7]);
                acc[2][0] = fma2(h2, w0, acc[2][0]); acc[2][1] = fma2(h2, w1, acc[2][1]);
                acc[2][2] = fma2(h2, w2, acc[2][2]); acc[2][3] = fma2(h2, w3, acc[2][3]);
                acc[2][4] = fma2(h2, w4, acc[2][4]); acc[2][5] = fma2(h2, w5, acc[2][5]);
                acc[2][6] = fma2(h2, w6, acc[2][6]); acc[2][7] = fma2(h2, w7, acc[2][7]);
                acc[3][0] = fma2(h3, w0, acc[3][0]); acc[3][1] = fma2(h3, w1, acc[3][1]);
                acc[3][2] = fma2(h3, w2, acc[3][2]); acc[3][3] = fma2(h3, w3, acc[3][3]);
                acc[3][4] = fma2(h3, w4, acc[3][4]); acc[3][5] = fma2(h3, w5, acc[3][5]);
                acc[3][6] = fma2(h3, w6, acc[3][6]); acc[3][7] = fma2(h3, w7, acc[3][7]);
            }
#pragma unroll
            for (int j = 0; j < 8; j++) {
                float m = 0.f;
#pragma unroll
                for (int p = 0; p < 4; p++) {
                    float lo, hi; unpack2(acc[p][j], lo, hi);
                    m = fmaxf(m, fmaxf(lo, hi));
                }
                m = fmaxf(m, __shfl_xor_sync(0xffffffffu, m, 8));
                m = fmaxf(m, __shfl_xor_sync(0xffffffffu, m, 16));
                if (kg == 0) {
                    int d = half * 64 + dg * 8 + j;
                    out[OUT_FEAT_BASE + (size_t)b * D3 * SS + (size_t)d * SS + s] = m;
                }
            }
        }
        __syncwarp();
    }
}

// ---------------------------------------------------------------------------
extern "C" void kernel_launch(void* const* d_in, const int* in_sizes, int n_in,
                              void* d_out, int out_size) {
    const float* xyz   = (const float*)d_in[0];
    const float* feats = (const float*)d_in[1];
    const float* W1    = (const float*)d_in[2];
    const float* b1    = (const float*)d_in[3];
    const float* W2    = (const float*)d_in[4];
    const float* b2    = (const float*)d_in[5];
    const float* W3    = (const float*)d_in[6];
    const float* b3    = (const float*)d_in[7];
    float* out = (float*)d_out;
    (void)in_sizes; (void)n_in; (void)out_size;

    cudaFuncSetAttribute(prep_all, cudaFuncAttributeMaxDynamicSharedMemorySize, PA_SMEM);
    cudaFuncSetAttribute(mlp_kernel, cudaFuncAttributeMaxDynamicSharedMemorySize, MLP_SMEM);

    prep_all<<<BB * (NN / 256), 256, PA_SMEM>>>(xyz, feats, W1, b1, out);
    ballq<<<BB * SS / 16, 512>>>();
    mlp_kernel<<<MGRID, MTHR, MLP_SMEM>>>(W1, W2, b2, W3, b3, out);
}